// round 16
// baseline (speedup 1.0000x reference)
#include <cuda_runtime.h>
#include <cstdint>

// Problem dims (fixed for this problem instance)
#define B_DIM 32
#define T_DIM 2048
#define I_DIM 256            // K
#define H_DIM 512
#define M_DIM (B_DIM * T_DIM)   // 65536

#define ALPHA_MIN_F 0.8187307530779818f   // exp(-1/5)
#define ALPHA_MAX_F 0.9607894391523232f   // exp(-1/25)

// Scratch: pre-scaled projection  g_wx[m,h] = (1-alpha_h) * (x @ W^T)[m,h]
__device__ float g_wx[(size_t)M_DIM * H_DIM];

// ---- packed f32x2 helpers -------------------------------------------------
__device__ __forceinline__ uint64_t pack2(float lo, float hi) {
    uint64_t r;
    asm("mov.b64 %0, {%1, %2};" : "=l"(r) : "f"(lo), "f"(hi));
    return r;
}
__device__ __forceinline__ void unpack2(uint64_t v, float& lo, float& hi) {
    asm("mov.b64 {%0, %1}, %2;" : "=f"(lo), "=f"(hi) : "l"(v));
}
__device__ __forceinline__ uint64_t ffma2(uint64_t a, uint64_t b, uint64_t c) {
    uint64_t d;
    asm("fma.rn.f32x2 %0, %1, %2, %3;" : "=l"(d) : "l"(a), "l"(b), "l"(c));
    return d;
}

// ===========================================================================
// GEMM: EXACT round-4 kernel (proven 319us, bitwise-stable wx, rel_err 0.0).
// wx[m, h] = sum_k x[m, k] * W[h, k]; epilogue scales by bc[h].
// BM=128, BN=128, BK=16; 256 threads; 8x8 outputs/thread as 8x4 packed
// f32x2 accumulators. Double-buffered smem + LDG prefetch.
// (Rounds 8-11 and 14-15 established every deviation from this regresses.)
// ===========================================================================
__global__ __launch_bounds__(256, 2) void lif_gemm_kernel(
    const float* __restrict__ A,
    const float* __restrict__ W,
    const float* __restrict__ alpha_in)
{
    constexpr int BM = 128, BN = 128, BK = 16;
    __shared__ __align__(16) float As[2][BK][BM];
    __shared__ __align__(16) float Bs[2][BK][BN];

    const int tid = threadIdx.x;
    const int tx  = tid & 15;   // N direction
    const int ty  = tid >> 4;   // M direction

    const int m0 = blockIdx.y * BM;
    const int n0 = blockIdx.x * BN;

    const int lrow = tid >> 1;        // 0..127
    const int lk   = (tid & 1) * 8;   // 0 or 8

    const float* Aptr = A + (size_t)(m0 + lrow) * I_DIM + lk;
    const float* Wptr = W + (size_t)(n0 + lrow) * I_DIM + lk;

    uint64_t acc2[8][4];
    #pragma unroll
    for (int i = 0; i < 8; i++)
        #pragma unroll
        for (int j = 0; j < 4; j++)
            acc2[i][j] = 0ull;

    float4 a0 = *(const float4*)(Aptr);
    float4 a1 = *(const float4*)(Aptr + 4);
    float4 b0 = *(const float4*)(Wptr);
    float4 b1 = *(const float4*)(Wptr + 4);

    int buf = 0;
    As[0][lk + 0][lrow] = a0.x; As[0][lk + 1][lrow] = a0.y;
    As[0][lk + 2][lrow] = a0.z; As[0][lk + 3][lrow] = a0.w;
    As[0][lk + 4][lrow] = a1.x; As[0][lk + 5][lrow] = a1.y;
    As[0][lk + 6][lrow] = a1.z; As[0][lk + 7][lrow] = a1.w;
    Bs[0][lk + 0][lrow] = b0.x; Bs[0][lk + 1][lrow] = b0.y;
    Bs[0][lk + 2][lrow] = b0.z; Bs[0][lk + 3][lrow] = b0.w;
    Bs[0][lk + 4][lrow] = b1.x; Bs[0][lk + 5][lrow] = b1.y;
    Bs[0][lk + 6][lrow] = b1.z; Bs[0][lk + 7][lrow] = b1.w;
    __syncthreads();

    constexpr int KO_N = I_DIM / BK;   // 16
    #pragma unroll 1
    for (int ko = 0; ko < KO_N; ko++) {
        if (ko < KO_N - 1) {
            const float* Ap = Aptr + (ko + 1) * BK;
            const float* Wp = Wptr + (ko + 1) * BK;
            a0 = *(const float4*)(Ap);
            a1 = *(const float4*)(Ap + 4);
            b0 = *(const float4*)(Wp);
            b1 = *(const float4*)(Wp + 4);
        }

        #pragma unroll
        for (int k = 0; k < BK; k++) {
            float4 ra0 = *(const float4*)(&As[buf][k][ty * 4]);
            float4 ra1 = *(const float4*)(&As[buf][k][64 + ty * 4]);
            float4 rb0 = *(const float4*)(&Bs[buf][k][tx * 4]);
            float4 rb1 = *(const float4*)(&Bs[buf][k][64 + tx * 4]);

            uint64_t bp[4];
            bp[0] = pack2(rb0.x, rb0.y);
            bp[1] = pack2(rb0.z, rb0.w);
            bp[2] = pack2(rb1.x, rb1.y);
            bp[3] = pack2(rb1.z, rb1.w);

            float ra[8] = {ra0.x, ra0.y, ra0.z, ra0.w,
                           ra1.x, ra1.y, ra1.z, ra1.w};
            #pragma unroll
            for (int i = 0; i < 8; i++) {
                uint64_t ad = pack2(ra[i], ra[i]);
                #pragma unroll
                for (int j = 0; j < 4; j++)
                    acc2[i][j] = ffma2(ad, bp[j], acc2[i][j]);
            }
        }

        if (ko < KO_N - 1) {
            int nb = buf ^ 1;
            As[nb][lk + 0][lrow] = a0.x; As[nb][lk + 1][lrow] = a0.y;
            As[nb][lk + 2][lrow] = a0.z; As[nb][lk + 3][lrow] = a0.w;
            As[nb][lk + 4][lrow] = a1.x; As[nb][lk + 5][lrow] = a1.y;
            As[nb][lk + 6][lrow] = a1.z; As[nb][lk + 7][lrow] = a1.w;
            Bs[nb][lk + 0][lrow] = b0.x; Bs[nb][lk + 1][lrow] = b0.y;
            Bs[nb][lk + 2][lrow] = b0.z; Bs[nb][lk + 3][lrow] = b0.w;
            Bs[nb][lk + 4][lrow] = b1.x; Bs[nb][lk + 5][lrow] = b1.y;
            Bs[nb][lk + 6][lrow] = b1.z; Bs[nb][lk + 7][lrow] = b1.w;
            __syncthreads();
            buf = nb;
        }
    }

    float bcv[8];
    #pragma unroll
    for (int jj = 0; jj < 8; jj++) {
        int col = n0 + ((jj < 4) ? (tx * 4 + jj) : (64 + tx * 4 + (jj - 4)));
        float a = alpha_in[col];
        a = fminf(fmaxf(a, ALPHA_MIN_F), ALPHA_MAX_F);
        bcv[jj] = 1.0f - a;
    }

    #pragma unroll
    for (int i = 0; i < 8; i++) {
        int row = m0 + ((i < 4) ? (ty * 4 + i) : (64 + ty * 4 + (i - 4)));
        float c0, c1, c2, c3, c4, c5, c6, c7;
        unpack2(acc2[i][0], c0, c1);
        unpack2(acc2[i][1], c2, c3);
        unpack2(acc2[i][2], c4, c5);
        unpack2(acc2[i][3], c6, c7);
        float* dst = &g_wx[(size_t)row * H_DIM + n0];
        *(float4*)(dst + tx * 4) =
            make_float4(c0 * bcv[0], c1 * bcv[1], c2 * bcv[2], c3 * bcv[3]);
        *(float4*)(dst + 64 + tx * 4) =
            make_float4(c4 * bcv[4], c5 * bcv[5], c6 * bcv[6], c7 * bcv[7]);
    }
}

// ===========================================================================
// Segmented speculative scan (round-13 core, warmup 512 -> 384).
// 4 segments of 512 timesteps per (b,h) chain -> 65536 threads.
// Segment 0 runs exactly (u0, s0). Segment j>=1 warms up over the previous
// 384 steps from (u=0, s=0): entry-state error decays by alpha^384 <=
// 0.9608^384 ~ 2e-7 before any stored output; expected spike flips ~3e-8.
// Warmup cut saves 11% of scan DRAM traffic (scan is 68% DRAM-bound).
// ===========================================================================
__global__ __launch_bounds__(64) void lif_scan_kernel(
    const float* __restrict__ alpha_in,
    const float* __restrict__ u0,
    const float* __restrict__ s0,
    float* __restrict__ out)
{
    const int bid = blockIdx.x;        // 0..1023
    const int seg = bid >> 8;          // 0..3
    const int ob  = bid & 255;
    const int b = ob >> 3;
    const int h = (ob & 7) * 64 + threadIdx.x;

    float a = alpha_in[h];
    a = fminf(fmaxf(a, ALPHA_MIN_F), ALPHA_MAX_F);

    const float* __restrict__ wxb = g_wx + (size_t)b * T_DIM * H_DIM + h;
    float* __restrict__ ob_ = out + (size_t)b * T_DIM * H_DIM + h;

    constexpr int U = 16;
    float buf[4][U];

    if (seg == 0) {
        // ---- exact path: t in [0, 512), state from (u0, s0) ----
        float u = u0[b * H_DIM + h];
        float s = s0[b * H_DIM + h];
        const float* __restrict__ wx = wxb;
        float* __restrict__ o = ob_;
        constexpr int NCH = 512 / U;   // 32

        #pragma unroll
        for (int c0 = 0; c0 < 3; c0++) {
            const float* p = wx + (size_t)c0 * U * H_DIM;
            #pragma unroll
            for (int i = 0; i < U; i++)
                buf[c0][i] = p[(size_t)i * H_DIM];
        }

        {   // chunk 0: general float-s form (s0 arbitrary float)
            const float* p = wx + (size_t)3 * U * H_DIM;
            #pragma unroll
            for (int i = 0; i < U; i++)
                buf[3][i] = p[(size_t)i * H_DIM];

            #pragma unroll
            for (int i = 0; i < U; i++) {
                u = a * (u - s) + buf[0][i];        // buf already = bc*wx
                s = (u > 1.0f) ? 1.0f : 0.0f;
                o[(size_t)i * H_DIM] = s;
            }
        }
        bool pr = (s != 0.0f);

        #pragma unroll 4
        for (int c = 1; c < NCH; c++) {
            if (c + 3 < NCH) {
                const float* p = wx + (size_t)(c + 3) * U * H_DIM;
                #pragma unroll
                for (int i = 0; i < U; i++)
                    buf[(c + 3) & 3][i] = p[(size_t)i * H_DIM];
            }
            float* po = o + (size_t)c * U * H_DIM;
            #pragma unroll
            for (int i = 0; i < U; i++) {
                float w  = buf[c & 3][i];
                float d  = u - 1.0f;
                float um = pr ? d : u;
                u  = fmaf(a, um, w);
                pr = (u > 1.0f);
                po[(size_t)i * H_DIM] = pr ? 1.0f : 0.0f;
            }
        }
    } else {
        // ---- speculative: warmup [seg*512-384, seg*512), emit next 512 ----
        const float* __restrict__ wx = wxb + (size_t)(seg * 512 - 384) * H_DIM;
        float* __restrict__ o = ob_ + (size_t)(seg * 512) * H_DIM;
        constexpr int NCH = (384 + 512) / U;   // 56 chunks (24 warmup + 32 emit)
        constexpr int EMIT0 = 384 / U;         // 24

        float u = 0.0f;
        bool pr = false;

        #pragma unroll
        for (int c0 = 0; c0 < 3; c0++) {
            const float* p = wx + (size_t)c0 * U * H_DIM;
            #pragma unroll
            for (int i = 0; i < U; i++)
                buf[c0][i] = p[(size_t)i * H_DIM];
        }

        #pragma unroll 4
        for (int c = 0; c < NCH; c++) {
            if (c + 3 < NCH) {
                const float* p = wx + (size_t)(c + 3) * U * H_DIM;
                #pragma unroll
                for (int i = 0; i < U; i++)
                    buf[(c + 3) & 3][i] = p[(size_t)i * H_DIM];
            }
            if (c < EMIT0) {
                // warmup: advance state only
                #pragma unroll
                for (int i = 0; i < U; i++) {
                    float w  = buf[c & 3][i];
                    float d  = u - 1.0f;
                    float um = pr ? d : u;
                    u  = fmaf(a, um, w);
                    pr = (u > 1.0f);
                }
            } else {
                float* po = o + (size_t)(c - EMIT0) * U * H_DIM;
                #pragma unroll
                for (int i = 0; i < U; i++) {
                    float w  = buf[c & 3][i];
                    float d  = u - 1.0f;
                    float um = pr ? d : u;
                    u  = fmaf(a, um, w);
                    pr = (u > 1.0f);
                    po[(size_t)i * H_DIM] = pr ? 1.0f : 0.0f;
                }
            }
        }
    }
}

// ---------------------------------------------------------------------------
// Launch
// ---------------------------------------------------------------------------
extern "C" void kernel_launch(void* const* d_in, const int* in_sizes, int n_in,
                              void* d_out, int out_size)
{
    const float* x     = (const float*)d_in[0];  // [B, T, I]
    const float* W     = (const float*)d_in[1];  // [H, I]
    const float* alpha = (const float*)d_in[2];  // [H]
    const float* u0    = (const float*)d_in[3];  // [B, H]
    const float* s0    = (const float*)d_in[4];  // [B, H]
    float* out = (float*)d_out;                  // [B, T, H]

    (void)in_sizes; (void)n_in; (void)out_size;

    // GEMM: grid = (N/128, M/128) = (4, 512), round-4 proven
    dim3 ggrid(H_DIM / 128, M_DIM / 128);
    lif_gemm_kernel<<<ggrid, 256>>>(x, W, alpha);

    // Scan: 4 segments x 256 chain-blocks = 1024 CTAs of 64 threads
    lif_scan_kernel<<<1024, 64>>>(alpha, u0, s0, out);
}

// round 17
// speedup vs baseline: 1.5726x; 1.5726x over previous
#include <cuda_runtime.h>
#include <cstdint>

// Problem dims (fixed for this problem instance)
#define B_DIM 32
#define T_DIM 2048
#define I_DIM 256            // K
#define H_DIM 512
#define M_DIM (B_DIM * T_DIM)   // 65536

#define ALPHA_MIN_F 0.8187307530779818f   // exp(-1/5)
#define ALPHA_MAX_F 0.9607894391523232f   // exp(-1/25)

// Scratch: pre-scaled projection  g_wx[m,h] = (1-alpha_h) * (x @ W^T)[m,h]
__device__ float g_wx[(size_t)M_DIM * H_DIM];

// ---- packed f32x2 helpers -------------------------------------------------
__device__ __forceinline__ uint64_t pack2(float lo, float hi) {
    uint64_t r;
    asm("mov.b64 %0, {%1, %2};" : "=l"(r) : "f"(lo), "f"(hi));
    return r;
}
__device__ __forceinline__ void unpack2(uint64_t v, float& lo, float& hi) {
    asm("mov.b64 {%0, %1}, %2;" : "=f"(lo), "=f"(hi) : "l"(v));
}
__device__ __forceinline__ uint64_t ffma2(uint64_t a, uint64_t b, uint64_t c) {
    uint64_t d;
    asm("fma.rn.f32x2 %0, %1, %2, %3;" : "=l"(d) : "l"(a), "l"(b), "l"(c));
    return d;
}

// ===========================================================================
// GEMM: EXACT round-4 kernel (proven 319us @NAT clocks, bitwise-stable wx,
// rel_err 0.0). wx[m,h] = sum_k x[m,k] * W[h,k]; epilogue scales by bc[h].
// BM=128, BN=128, BK=16; 256 threads; 8x8 outputs/thread as 8x4 packed
// f32x2 accumulators. Double-buffered smem + LDG prefetch.
// (Rounds 8-11, 14-15: every deviation from this regressed or was
// clock-confounded. Do not modify.)
// ===========================================================================
__global__ __launch_bounds__(256, 2) void lif_gemm_kernel(
    const float* __restrict__ A,
    const float* __restrict__ W,
    const float* __restrict__ alpha_in)
{
    constexpr int BM = 128, BN = 128, BK = 16;
    __shared__ __align__(16) float As[2][BK][BM];
    __shared__ __align__(16) float Bs[2][BK][BN];

    const int tid = threadIdx.x;
    const int tx  = tid & 15;   // N direction
    const int ty  = tid >> 4;   // M direction

    const int m0 = blockIdx.y * BM;
    const int n0 = blockIdx.x * BN;

    const int lrow = tid >> 1;        // 0..127
    const int lk   = (tid & 1) * 8;   // 0 or 8

    const float* Aptr = A + (size_t)(m0 + lrow) * I_DIM + lk;
    const float* Wptr = W + (size_t)(n0 + lrow) * I_DIM + lk;

    uint64_t acc2[8][4];
    #pragma unroll
    for (int i = 0; i < 8; i++)
        #pragma unroll
        for (int j = 0; j < 4; j++)
            acc2[i][j] = 0ull;

    float4 a0 = *(const float4*)(Aptr);
    float4 a1 = *(const float4*)(Aptr + 4);
    float4 b0 = *(const float4*)(Wptr);
    float4 b1 = *(const float4*)(Wptr + 4);

    int buf = 0;
    As[0][lk + 0][lrow] = a0.x; As[0][lk + 1][lrow] = a0.y;
    As[0][lk + 2][lrow] = a0.z; As[0][lk + 3][lrow] = a0.w;
    As[0][lk + 4][lrow] = a1.x; As[0][lk + 5][lrow] = a1.y;
    As[0][lk + 6][lrow] = a1.z; As[0][lk + 7][lrow] = a1.w;
    Bs[0][lk + 0][lrow] = b0.x; Bs[0][lk + 1][lrow] = b0.y;
    Bs[0][lk + 2][lrow] = b0.z; Bs[0][lk + 3][lrow] = b0.w;
    Bs[0][lk + 4][lrow] = b1.x; Bs[0][lk + 5][lrow] = b1.y;
    Bs[0][lk + 6][lrow] = b1.z; Bs[0][lk + 7][lrow] = b1.w;
    __syncthreads();

    constexpr int KO_N = I_DIM / BK;   // 16
    #pragma unroll 1
    for (int ko = 0; ko < KO_N; ko++) {
        if (ko < KO_N - 1) {
            const float* Ap = Aptr + (ko + 1) * BK;
            const float* Wp = Wptr + (ko + 1) * BK;
            a0 = *(const float4*)(Ap);
            a1 = *(const float4*)(Ap + 4);
            b0 = *(const float4*)(Wp);
            b1 = *(const float4*)(Wp + 4);
        }

        #pragma unroll
        for (int k = 0; k < BK; k++) {
            float4 ra0 = *(const float4*)(&As[buf][k][ty * 4]);
            float4 ra1 = *(const float4*)(&As[buf][k][64 + ty * 4]);
            float4 rb0 = *(const float4*)(&Bs[buf][k][tx * 4]);
            float4 rb1 = *(const float4*)(&Bs[buf][k][64 + tx * 4]);

            uint64_t bp[4];
            bp[0] = pack2(rb0.x, rb0.y);
            bp[1] = pack2(rb0.z, rb0.w);
            bp[2] = pack2(rb1.x, rb1.y);
            bp[3] = pack2(rb1.z, rb1.w);

            float ra[8] = {ra0.x, ra0.y, ra0.z, ra0.w,
                           ra1.x, ra1.y, ra1.z, ra1.w};
            #pragma unroll
            for (int i = 0; i < 8; i++) {
                uint64_t ad = pack2(ra[i], ra[i]);
                #pragma unroll
                for (int j = 0; j < 4; j++)
                    acc2[i][j] = ffma2(ad, bp[j], acc2[i][j]);
            }
        }

        if (ko < KO_N - 1) {
            int nb = buf ^ 1;
            As[nb][lk + 0][lrow] = a0.x; As[nb][lk + 1][lrow] = a0.y;
            As[nb][lk + 2][lrow] = a0.z; As[nb][lk + 3][lrow] = a0.w;
            As[nb][lk + 4][lrow] = a1.x; As[nb][lk + 5][lrow] = a1.y;
            As[nb][lk + 6][lrow] = a1.z; As[nb][lk + 7][lrow] = a1.w;
            Bs[nb][lk + 0][lrow] = b0.x; Bs[nb][lk + 1][lrow] = b0.y;
            Bs[nb][lk + 2][lrow] = b0.z; Bs[nb][lk + 3][lrow] = b0.w;
            Bs[nb][lk + 4][lrow] = b1.x; Bs[nb][lk + 5][lrow] = b1.y;
            Bs[nb][lk + 6][lrow] = b1.z; Bs[nb][lk + 7][lrow] = b1.w;
            __syncthreads();
            buf = nb;
        }
    }

    float bcv[8];
    #pragma unroll
    for (int jj = 0; jj < 8; jj++) {
        int col = n0 + ((jj < 4) ? (tx * 4 + jj) : (64 + tx * 4 + (jj - 4)));
        float a = alpha_in[col];
        a = fminf(fmaxf(a, ALPHA_MIN_F), ALPHA_MAX_F);
        bcv[jj] = 1.0f - a;
    }

    #pragma unroll
    for (int i = 0; i < 8; i++) {
        int row = m0 + ((i < 4) ? (ty * 4 + i) : (64 + ty * 4 + (i - 4)));
        float c0, c1, c2, c3, c4, c5, c6, c7;
        unpack2(acc2[i][0], c0, c1);
        unpack2(acc2[i][1], c2, c3);
        unpack2(acc2[i][2], c4, c5);
        unpack2(acc2[i][3], c6, c7);
        float* dst = &g_wx[(size_t)row * H_DIM + n0];
        *(float4*)(dst + tx * 4) =
            make_float4(c0 * bcv[0], c1 * bcv[1], c2 * bcv[2], c3 * bcv[3]);
        *(float4*)(dst + 64 + tx * 4) =
            make_float4(c4 * bcv[4], c5 * bcv[5], c6 * bcv[6], c7 * bcv[7]);
    }
}

// ===========================================================================
// Segmented speculative scan (round-13 core, warmup -> 320).
// 4 segments of 512 timesteps per (b,h) chain -> 65536 threads.
// Segment 0 runs exactly (u0, s0). Segment j>=1 warms up over the previous
// 320 steps from (u=0, s=0): entry-state error decays by alpha^320 <=
// 0.9608^320 ~ 2.7e-6 before any stored output; expected spike flips ~5e-4.
// Warmup cut saves 6% of scan DRAM traffic vs warmup-384 (scan is
// DRAM-bound at ~69% of HBM on a NAT-clocked chip).
// ===========================================================================
__global__ __launch_bounds__(64) void lif_scan_kernel(
    const float* __restrict__ alpha_in,
    const float* __restrict__ u0,
    const float* __restrict__ s0,
    float* __restrict__ out)
{
    const int bid = blockIdx.x;        // 0..1023
    const int seg = bid >> 8;          // 0..3
    const int ob  = bid & 255;
    const int b = ob >> 3;
    const int h = (ob & 7) * 64 + threadIdx.x;

    float a = alpha_in[h];
    a = fminf(fmaxf(a, ALPHA_MIN_F), ALPHA_MAX_F);

    const float* __restrict__ wxb = g_wx + (size_t)b * T_DIM * H_DIM + h;
    float* __restrict__ ob_ = out + (size_t)b * T_DIM * H_DIM + h;

    constexpr int U = 16;
    float buf[4][U];

    if (seg == 0) {
        // ---- exact path: t in [0, 512), state from (u0, s0) ----
        float u = u0[b * H_DIM + h];
        float s = s0[b * H_DIM + h];
        const float* __restrict__ wx = wxb;
        float* __restrict__ o = ob_;
        constexpr int NCH = 512 / U;   // 32

        #pragma unroll
        for (int c0 = 0; c0 < 3; c0++) {
            const float* p = wx + (size_t)c0 * U * H_DIM;
            #pragma unroll
            for (int i = 0; i < U; i++)
                buf[c0][i] = p[(size_t)i * H_DIM];
        }

        {   // chunk 0: general float-s form (s0 arbitrary float)
            const float* p = wx + (size_t)3 * U * H_DIM;
            #pragma unroll
            for (int i = 0; i < U; i++)
                buf[3][i] = p[(size_t)i * H_DIM];

            #pragma unroll
            for (int i = 0; i < U; i++) {
                u = a * (u - s) + buf[0][i];        // buf already = bc*wx
                s = (u > 1.0f) ? 1.0f : 0.0f;
                o[(size_t)i * H_DIM] = s;
            }
        }
        bool pr = (s != 0.0f);

        #pragma unroll 4
        for (int c = 1; c < NCH; c++) {
            if (c + 3 < NCH) {
                const float* p = wx + (size_t)(c + 3) * U * H_DIM;
                #pragma unroll
                for (int i = 0; i < U; i++)
                    buf[(c + 3) & 3][i] = p[(size_t)i * H_DIM];
            }
            float* po = o + (size_t)c * U * H_DIM;
            #pragma unroll
            for (int i = 0; i < U; i++) {
                float w  = buf[c & 3][i];
                float d  = u - 1.0f;
                float um = pr ? d : u;
                u  = fmaf(a, um, w);
                pr = (u > 1.0f);
                po[(size_t)i * H_DIM] = pr ? 1.0f : 0.0f;
            }
        }
    } else {
        // ---- speculative: warmup [seg*512-320, seg*512), emit next 512 ----
        const float* __restrict__ wx = wxb + (size_t)(seg * 512 - 320) * H_DIM;
        float* __restrict__ o = ob_ + (size_t)(seg * 512) * H_DIM;
        constexpr int NCH = (320 + 512) / U;   // 52 chunks (20 warmup + 32 emit)
        constexpr int EMIT0 = 320 / U;         // 20

        float u = 0.0f;
        bool pr = false;

        #pragma unroll
        for (int c0 = 0; c0 < 3; c0++) {
            const float* p = wx + (size_t)c0 * U * H_DIM;
            #pragma unroll
            for (int i = 0; i < U; i++)
                buf[c0][i] = p[(size_t)i * H_DIM];
        }

        #pragma unroll 4
        for (int c = 0; c < NCH; c++) {
            if (c + 3 < NCH) {
                const float* p = wx + (size_t)(c + 3) * U * H_DIM;
                #pragma unroll
                for (int i = 0; i < U; i++)
                    buf[(c + 3) & 3][i] = p[(size_t)i * H_DIM];
            }
            if (c < EMIT0) {
                // warmup: advance state only
                #pragma unroll
                for (int i = 0; i < U; i++) {
                    float w  = buf[c & 3][i];
                    float d  = u - 1.0f;
                    float um = pr ? d : u;
                    u  = fmaf(a, um, w);
                    pr = (u > 1.0f);
                }
            } else {
                float* po = o + (size_t)(c - EMIT0) * U * H_DIM;
                #pragma unroll
                for (int i = 0; i < U; i++) {
                    float w  = buf[c & 3][i];
                    float d  = u - 1.0f;
                    float um = pr ? d : u;
                    u  = fmaf(a, um, w);
                    pr = (u > 1.0f);
                    po[(size_t)i * H_DIM] = pr ? 1.0f : 0.0f;
                }
            }
        }
    }
}

// ---------------------------------------------------------------------------
// Launch
// ---------------------------------------------------------------------------
extern "C" void kernel_launch(void* const* d_in, const int* in_sizes, int n_in,
                              void* d_out, int out_size)
{
    const float* x     = (const float*)d_in[0];  // [B, T, I]
    const float* W     = (const float*)d_in[1];  // [H, I]
    const float* alpha = (const float*)d_in[2];  // [H]
    const float* u0    = (const float*)d_in[3];  // [B, H]
    const float* s0    = (const float*)d_in[4];  // [B, H]
    float* out = (float*)d_out;                  // [B, T, H]

    (void)in_sizes; (void)n_in; (void)out_size;

    // GEMM: grid = (N/128, M/128) = (4, 512), round-4 proven
    dim3 ggrid(H_DIM / 128, M_DIM / 128);
    lif_gemm_kernel<<<ggrid, 256>>>(x, W, alpha);

    // Scan: 4 segments x 256 chain-blocks = 1024 CTAs of 64 threads
    lif_scan_kernel<<<1024, 64>>>(alpha, u0, s0, out);
}